// round 1
// baseline (speedup 1.0000x reference)
#include <cuda_runtime.h>
#include <cstdint>

// Problem constants
#define BATCH   8
#define NPTS    200000
#define NCH     32
#define RES     128
#define RR      (RES * RES)       // 16384
#define NPLANES 3
#define NBP     (BATCH * NPLANES) // 24

// Scratch: channel-contiguous accumulator so vector atomics hit 16B-aligned,
// cache-friendly 128B bins. ~50.3 MB + 1.5 MB counts (static device arrays;
// allocation-free per harness rules).
__device__ __align__(128) float g_acc[(size_t)NBP * RR * NCH];
__device__ __align__(128) float g_cnt[(size_t)NBP * RR];

__device__ __forceinline__ void red_add_v4(float* addr, float a, float b, float c, float d) {
    asm volatile("red.global.add.v4.f32 [%0], {%1, %2, %3, %4};"
                 :: "l"(addr), "f"(a), "f"(b), "f"(c), "f"(d) : "memory");
}
__device__ __forceinline__ void red_add_f32(float* addr, float v) {
    asm volatile("red.global.add.f32 [%0], %1;" :: "l"(addr), "f"(v) : "memory");
}

// ---------------------------------------------------------------------------
// Kernel 1: zero the accumulators (output itself is fully overwritten later).
// ---------------------------------------------------------------------------
__global__ void __launch_bounds__(256) zero_kernel() {
    const size_t stride = (size_t)gridDim.x * blockDim.x;
    size_t tid = (size_t)blockIdx.x * blockDim.x + threadIdx.x;
    const float4 z = {0.f, 0.f, 0.f, 0.f};

    float4* a = reinterpret_cast<float4*>(g_acc);
    const size_t n_acc4 = (size_t)NBP * RR * NCH / 4;   // 3,145,728
    for (size_t j = tid; j < n_acc4; j += stride) a[j] = z;

    float4* c = reinterpret_cast<float4*>(g_cnt);
    const size_t n_cnt4 = (size_t)NBP * RR / 4;         // 98,304
    for (size_t j = tid; j < n_cnt4; j += stride) c[j] = z;
}

// ---------------------------------------------------------------------------
// Kernel 2: per-point scatter. One thread per (b, n) point.
//   - coalesced feature reads (consecutive n across warp for each channel)
//   - 3 count reds + 24 v4 vector reds per point (fire-and-forget REDG path)
// ---------------------------------------------------------------------------
__global__ void __launch_bounds__(256) scatter_kernel(const float* __restrict__ xyz,
                                                      const float* __restrict__ feat) {
    const int gid = blockIdx.x * 256 + threadIdx.x;
    if (gid >= BATCH * NPTS) return;
    const int b = gid / NPTS;
    const int n = gid - b * NPTS;

    // xyz layout (B, N, 3)
    const float* p = xyz + (size_t)gid * 3;
    const float px = p[0], py = p[1], pz = p[2];

    // Mirror reference math exactly:
    //   xyz_norm = (p + 1)/2 - 0.5 ; u = xyz_norm/(1+eps) + 0.5 ; clip [0, 1-eps) ; floor(u*128)
    const float DEN = 1.0f + 1e-5f;
    const float CLMP = 1.0f - 1e-5f;
    auto bin_of = [&](float v) -> int {
        float u = ((v + 1.0f) * 0.5f - 0.5f) / DEN + 0.5f;
        u = fminf(fmaxf(u, 0.0f), CLMP);
        return (int)(u * (float)RES);
    };
    const int ix = bin_of(px);
    const int iy = bin_of(py);
    const int iz = bin_of(pz);

    // plane dims: xy=(0,1), yz=(1,2), xz=(0,2); lin = idx[d0] + R*idx[d1]
    const int lin0 = ix + RES * iy;   // xy
    const int lin1 = iy + RES * iz;   // yz
    const int lin2 = ix + RES * iz;   // xz

    const int bp = b * NPLANES;
    red_add_f32(&g_cnt[(size_t)(bp + 0) * RR + lin0], 1.0f);
    red_add_f32(&g_cnt[(size_t)(bp + 1) * RR + lin1], 1.0f);
    red_add_f32(&g_cnt[(size_t)(bp + 2) * RR + lin2], 1.0f);

    float* a0 = g_acc + ((size_t)(bp + 0) * RR + lin0) * NCH;
    float* a1 = g_acc + ((size_t)(bp + 1) * RR + lin1) * NCH;
    float* a2 = g_acc + ((size_t)(bp + 2) * RR + lin2) * NCH;

    // feature layout (B, C, N): stride N between channels, coalesced in n
    const float* f = feat + (size_t)b * NCH * NPTS + n;

#pragma unroll
    for (int c = 0; c < NCH; c += 4) {
        const float v0 = f[(size_t)(c + 0) * NPTS];
        const float v1 = f[(size_t)(c + 1) * NPTS];
        const float v2 = f[(size_t)(c + 2) * NPTS];
        const float v3 = f[(size_t)(c + 3) * NPTS];
        red_add_v4(a0 + c, v0, v1, v2, v3);
        red_add_v4(a1 + c, v0, v1, v2, v3);
        red_add_v4(a2 + c, v0, v1, v2, v3);
    }
}

// ---------------------------------------------------------------------------
// Kernel 3: finalize. Transpose [bin][c] -> [c][bin] via padded smem tile and
// divide by max(count, 1). Block = 256 threads handles 128 bins of one (b,plane).
// ---------------------------------------------------------------------------
__global__ void __launch_bounds__(256) finalize_kernel(float* __restrict__ out) {
    __shared__ float s[128 * 33];     // pad 33 to avoid 32-way bank conflicts
    __shared__ float sinv[128];

    const int tiles_per_bp = RR / 128;             // 128
    const int bp   = blockIdx.x / tiles_per_bp;    // 0..23
    const int tile = blockIdx.x % tiles_per_bp;    // 0..127
    const int bin0 = tile * 128;

    // Coalesced load of 128 bins x 32 channels (contiguous in g_acc)
    const float* accbase = g_acc + ((size_t)bp * RR + bin0) * NCH;
    for (int j = threadIdx.x; j < 128 * NCH; j += 256) {
        const int i = j >> 5;       // bin within tile
        const int c = j & 31;       // channel
        s[i * 33 + c] = accbase[j];
    }
    for (int i = threadIdx.x; i < 128; i += 256) {
        const float cnt = g_cnt[(size_t)bp * RR + bin0 + i];
        sinv[i] = 1.0f / fmaxf(cnt, 1.0f);
    }
    __syncthreads();

    // Coalesced store: out[((bp)*C + c)*RR + bin0 + i]
    float* ob = out + (size_t)bp * NCH * RR + bin0;
    for (int j = threadIdx.x; j < 128 * NCH; j += 256) {
        const int c = j >> 7;       // channel
        const int i = j & 127;      // bin within tile
        ob[(size_t)c * RR + i] = s[i * 33 + c] * sinv[i];
    }
}

// ---------------------------------------------------------------------------
extern "C" void kernel_launch(void* const* d_in, const int* in_sizes, int n_in,
                              void* d_out, int out_size) {
    const float* xyz  = (const float*)d_in[0];  // (B, N, 3)
    const float* feat = (const float*)d_in[1];  // (B, C, N)
    float* out = (float*)d_out;                 // (B, 3, C, R, R)

    zero_kernel<<<1024, 256>>>();

    const int npoints = BATCH * NPTS;
    scatter_kernel<<<(npoints + 255) / 256, 256>>>(xyz, feat);

    finalize_kernel<<<NBP * (RR / 128), 256>>>(out);
}